// round 13
// baseline (speedup 1.0000x reference)
#include <cuda_runtime.h>
#include <cstdint>
#include <math.h>

#define BB 64
#define LL 200
#define HH 128
#define SS 64
#define EE 256
#define NBLK 2
#define MM (BB*LL)
#define KC 101
#define LDSSM 192
#define LDXZ (2*EE)

// TF32 round-to-nearest (matches tensor-core operand conversion).
__device__ __forceinline__ float tf32r(float x) {
    float r;
    asm("cvt.rna.tf32.f32 %0, %1;" : "=f"(r) : "f"(x));
    return r;
}

__device__ __forceinline__ void mma_tf32(float c[4],
    uint32_t a0, uint32_t a1, uint32_t a2, uint32_t a3,
    uint32_t b0, uint32_t b1) {
    asm volatile(
        "mma.sync.aligned.m16n8k8.row.col.f32.tf32.tf32.f32 "
        "{%0,%1,%2,%3}, {%4,%5,%6,%7}, {%8,%9}, {%0,%1,%2,%3};\n"
        : "+f"(c[0]), "+f"(c[1]), "+f"(c[2]), "+f"(c[3])
        : "r"(a0), "r"(a1), "r"(a2), "r"(a3), "r"(b0), "r"(b1));
}

__device__ __forceinline__ float wredsum(float v) {
#pragma unroll
    for (int o = 16; o; o >>= 1) v += __shfl_xor_sync(0xffffffffu, v, o);
    return v;
}

__device__ __forceinline__ void cp16(void* dst, const void* src) {
    uint32_t d = (uint32_t)__cvta_generic_to_shared(dst);
    asm volatile("cp.async.ca.shared.global [%0], [%1], 16;\n" :: "r"(d), "l"(src));
}

// Scratch (device globals — no allocation allowed)
__device__ __align__(16) float g_x[MM*HH];
__device__ __align__(16) float g_u[MM*HH];      // pre-rounded tf32
__device__ __align__(16) float g_xz[MM*LDXZ];
__device__ __align__(16) float g_xc[MM*EE];     // exact (for act D*x)
__device__ __align__(16) float g_xcr[MM*EE];    // tf32-rounded (GEMM A operand)
__device__ __align__(16) float g_ssm[MM*LDSSM]; // [delta_raw | B_raw | C]
__device__ __align__(16) float g_y[MM*EE];      // pre-rounded tf32
__device__ __align__(16) float g_xsum[MM];
__device__ __align__(16) float g_s[MM];
// pre-rounded weights: [in_w (2*128*512) | xproj_w (2*256*192) | out_w (2*256*128)]
#define WR_INW   0
#define WR_XPROJ 131072
#define WR_OUTW  229376
__device__ __align__(16) float g_wrnd[294912];

// ---------------------------------------------------------------------------
// Pre-round the three weight tensors to tf32 (once per launch; amortized).
__global__ void roundw_kernel(const float4* __restrict__ a, int na4,
                              const float4* __restrict__ b, int nb4,
                              const float4* __restrict__ c, int nc4,
                              float4* __restrict__ dst) {
    int i = blockIdx.x * blockDim.x + threadIdx.x;
    const float4* s; int off;
    if (i < na4) { s = a; off = i; }
    else if (i < na4 + nb4) { s = b; off = i - na4; }
    else if (i < na4 + nb4 + nc4) { s = c; off = i - na4 - nb4; }
    else return;
    float4 v = s[off];
    v.x = tf32r(v.x); v.y = tf32r(v.y); v.z = tf32r(v.z); v.w = tf32r(v.w);
    dst[i] = v;
}

// Fused embed + first-block LayerNorm. Warp per row, float4, 8 rows/CTA.
// u stored tf32-rounded (feeds GEMM only).
__global__ void __launch_bounds__(256) embed_ln_kernel(
    const int* __restrict__ seqs,
    const float* __restrict__ item_emb, const float* __restrict__ pos_emb,
    const float* __restrict__ g, const float* __restrict__ b,
    float* __restrict__ x, float* __restrict__ u) {
    int warp = threadIdx.x >> 5, lane = threadIdx.x & 31;
    int m = blockIdx.x * 8 + warp;
    int l = m % LL;
    int id = seqs[m];
    int e = lane << 2;
    float4 ie = *(const float4*)(item_emb + (size_t)id * HH + e);
    float4 pe = *(const float4*)(pos_emb + l * HH + e);
    float msk = (id != 0) ? 1.f : 0.f;
    float4 v;
    v.x = (ie.x + pe.x) * msk; v.y = (ie.y + pe.y) * msk;
    v.z = (ie.z + pe.z) * msk; v.w = (ie.w + pe.w) * msk;
    *(float4*)(x + (size_t)m * HH + e) = v;
    float mean = wredsum(v.x + v.y + v.z + v.w) * (1.f / HH);
    float4 d; d.x = v.x - mean; d.y = v.y - mean; d.z = v.z - mean; d.w = v.w - mean;
    float var = wredsum(d.x * d.x + d.y * d.y + d.z * d.z + d.w * d.w) * (1.f / HH);
    float inv = rsqrtf(var + 1e-5f);
    float4 gg = *(const float4*)(g + e);
    float4 bb = *(const float4*)(b + e);
    float4 o;
    o.x = tf32r(d.x * inv * gg.x + bb.x); o.y = tf32r(d.y * inv * gg.y + bb.y);
    o.z = tf32r(d.z * inv * gg.z + bb.z); o.w = tf32r(d.w * inv * gg.w + bb.w);
    *(float4*)(u + (size_t)m * HH + e) = o;
}

// LayerNorm over H=128. Warp per row, float4, 8 rows/CTA. u tf32-rounded.
__global__ void __launch_bounds__(256) ln128_kernel(
    const float* __restrict__ x, float* __restrict__ u,
    const float* __restrict__ g, const float* __restrict__ b) {
    int warp = threadIdx.x >> 5, lane = threadIdx.x & 31;
    int m = blockIdx.x * 8 + warp;
    int e = lane << 2;
    float4 v = *(const float4*)(x + (size_t)m * HH + e);
    float mean = wredsum(v.x + v.y + v.z + v.w) * (1.f / HH);
    float4 d; d.x = v.x - mean; d.y = v.y - mean; d.z = v.z - mean; d.w = v.w - mean;
    float var = wredsum(d.x * d.x + d.y * d.y + d.z * d.z + d.w * d.w) * (1.f / HH);
    float inv = rsqrtf(var + 1e-5f);
    float4 gg = *(const float4*)(g + e);
    float4 bb = *(const float4*)(b + e);
    float4 o;
    o.x = tf32r(d.x * inv * gg.x + bb.x); o.y = tf32r(d.y * inv * gg.y + bb.y);
    o.z = tf32r(d.z * inv * gg.z + bb.z); o.w = tf32r(d.w * inv * gg.w + bb.w);
    *(float4*)(u + (size_t)m * HH + e) = o;
}

// ---------------------------------------------------------------------------
// TF32 tensor-core GEMM, 3-stage cp.async pipeline. Operands PRE-ROUNDED.
// BM=128, BN=64, BK=16; 8 warps (4m x 2n), warp tile 32x32 via m16n8k8.
// epi==1: C = (resid + C + bias) * mask (residual in C).
#define APAD 20
#define BPAD 72
#define STG 3
__global__ void __launch_bounds__(256) gemm_tc_kernel(
    const float* __restrict__ A, int lda,
    const float* __restrict__ W, int ldw,
    const float* __restrict__ bias,
    float* __restrict__ C, int ldc,
    int Kdim, int epi, const int* __restrict__ seqs)
{
    __shared__ __align__(16) float As[STG][128 * APAD];
    __shared__ __align__(16) float Ws[STG][16 * BPAD];
    int tid = threadIdx.x;
    int m0 = blockIdx.y << 7, n0 = blockIdx.x << 6;
    int lane = tid & 31, wid = tid >> 5;
    int wm = (wid & 3) << 5;
    int wn = (wid >> 2) << 5;
    int g = lane >> 2, cq = lane & 3;
    int nk = Kdim >> 4;

    // async copy of k-tile kt into stage s
    auto stage_copy = [&](int s, int kt) {
#pragma unroll
        for (int j = 0; j < 2; j++) {
            int c = tid + (j << 8);           // 0..511
            int r = c >> 2, q = (c & 3) << 2;
            cp16(&As[s][r * APAD + q], A + (size_t)(m0 + r) * lda + (kt << 4) + q);
        }
        {
            int k = tid >> 4, q = (tid & 15) << 2;
            cp16(&Ws[s][k * BPAD + q], W + (size_t)((kt << 4) + k) * ldw + n0 + q);
        }
        asm volatile("cp.async.commit_group;\n");
    };

    float acc[2][4][4];
#pragma unroll
    for (int i = 0; i < 2; i++)
#pragma unroll
        for (int j = 0; j < 4; j++)
#pragma unroll
            for (int q = 0; q < 4; q++) acc[i][j][q] = 0.f;

    stage_copy(0, 0);
    if (nk > 1) stage_copy(1, 1);

    int cur = 0;
    for (int kt = 0; kt < nk; kt++) {
        if (kt < nk - 1) asm volatile("cp.async.wait_group 1;\n");
        else             asm volatile("cp.async.wait_group 0;\n");
        __syncthreads();
        if (kt + 2 < nk) {
            int nxt = cur + 2; if (nxt >= STG) nxt -= STG;
            stage_copy(nxt, kt + 2);
        }
#pragma unroll
        for (int ks = 0; ks < 2; ks++) {
            int kk = ks << 3;
            uint32_t bf[4][2];
#pragma unroll
            for (int j = 0; j < 4; j++) {
                bf[j][0] = __float_as_uint(Ws[cur][(kk + cq) * BPAD + wn + (j << 3) + g]);
                bf[j][1] = __float_as_uint(Ws[cur][(kk + cq + 4) * BPAD + wn + (j << 3) + g]);
            }
#pragma unroll
            for (int i = 0; i < 2; i++) {
                const float* ab = &As[cur][(wm + (i << 4)) * APAD + kk + cq];
                uint32_t a0 = __float_as_uint(ab[g * APAD]);
                uint32_t a1 = __float_as_uint(ab[(g + 8) * APAD]);
                uint32_t a2 = __float_as_uint(ab[g * APAD + 4]);
                uint32_t a3 = __float_as_uint(ab[(g + 8) * APAD + 4]);
#pragma unroll
                for (int j = 0; j < 4; j++)
                    mma_tf32(acc[i][j], a0, a1, a2, a3, bf[j][0], bf[j][1]);
            }
        }
        if (++cur == STG) cur = 0;
    }

#pragma unroll
    for (int i = 0; i < 2; i++) {
        int r0 = m0 + wm + (i << 4) + g;
        int r1 = r0 + 8;
        float msk0 = 1.f, msk1 = 1.f;
        if (epi == 1) {
            msk0 = (seqs[r0] != 0) ? 1.f : 0.f;
            msk1 = (seqs[r1] != 0) ? 1.f : 0.f;
        }
#pragma unroll
        for (int j = 0; j < 4; j++) {
            int col = n0 + wn + (j << 3) + (cq << 1);
            float b0 = bias[col], b1 = bias[col + 1];
            size_t o0 = (size_t)r0 * ldc + col;
            size_t o1 = (size_t)r1 * ldc + col;
            float v00 = acc[i][j][0] + b0, v01 = acc[i][j][1] + b1;
            float v10 = acc[i][j][2] + b0, v11 = acc[i][j][3] + b1;
            if (epi == 1) {
                v00 = (C[o0] + v00) * msk0; v01 = (C[o0 + 1] + v01) * msk0;
                v10 = (C[o1] + v10) * msk1; v11 = (C[o1 + 1] + v11) * msk1;
            }
            C[o0] = v00; C[o0 + 1] = v01;
            C[o1] = v10; C[o1 + 1] = v11;
        }
    }
}

// depthwise conv k=3 pad (1,1) + silu + row-sum. Warp per row, 8 rows/CTA.
// Writes xc (exact, for act's D*x) and xcr (tf32-rounded, GEMM A operand).
__global__ void __launch_bounds__(256) conv_kernel(
    const float* __restrict__ xz,
    const float* __restrict__ cw, const float* __restrict__ cb,
    float* __restrict__ xc, float* __restrict__ xcr, float* __restrict__ xsum) {
    int warp = threadIdx.x >> 5, lane = threadIdx.x & 31;
    int m = blockIdx.x * 8 + warp;
    int l = m % LL;
    const float* xr = xz + (size_t)m * LDXZ;
    float s = 0.f;
#pragma unroll
    for (int h = 0; h < 2; h++) {
        int e = (lane << 3) + (h << 2);
        float4 vm = *(const float4*)(xr + e);
        float4 vl = (l > 0) ? *(const float4*)(xr - LDXZ + e) : make_float4(0.f, 0.f, 0.f, 0.f);
        float4 vh = (l < LL - 1) ? *(const float4*)(xr + LDXZ + e) : make_float4(0.f, 0.f, 0.f, 0.f);
        float am[4] = {vm.x, vm.y, vm.z, vm.w};
        float al[4] = {vl.x, vl.y, vl.z, vl.w};
        float ah[4] = {vh.x, vh.y, vh.z, vh.w};
        float out[4], outr[4];
#pragma unroll
        for (int j = 0; j < 4; j++) {
            int ee = e + j;
            float acc = tf32r(am[j]) * tf32r(cw[ee * 3 + 1]);
            acc += tf32r(al[j]) * tf32r(cw[ee * 3 + 0]);
            acc += tf32r(ah[j]) * tf32r(cw[ee * 3 + 2]);
            acc += cb[ee];
            float sv = acc / (1.f + __expf(-acc));
            out[j] = sv;
            outr[j] = tf32r(sv);
            s += sv;
        }
        *(float4*)(xc + (size_t)m * EE + e) = make_float4(out[0], out[1], out[2], out[3]);
        *(float4*)(xcr + (size_t)m * EE + e) = make_float4(outr[0], outr[1], outr[2], outr[3]);
    }
    s = wredsum(s);
    if (lane == 0) xsum[m] = s;
}

// Sequential scan with fused softplus/dB. Aj pre-scaled by log2(e).
__global__ void __launch_bounds__(256) scan_kernel(
    const float* __restrict__ ssm, const float* __restrict__ xsum,
    const float* __restrict__ A_log, float* __restrict__ sout, int lastonly)
{
    int b = blockIdx.x, tid = threadIdx.x;
    __shared__ float A_sh[SS];
    __shared__ __align__(16) float gbuf[2][SS];
    __shared__ float psum[8];
    if (tid < SS) {
        float al = A_log[tid];
        al = fminf(fmaxf(al, -5.f), 5.f);
        A_sh[tid] = -expf(al) * 1.44269504088896340736f;   // A * log2(e)
        gbuf[0][tid] = 0.f;
    }
    __syncthreads();
    int i = tid >> 2, sub = tid & 3;
    float Aj[16];
#pragma unroll
    for (int q = 0; q < 16; q++) Aj[q] = A_sh[sub * 16 + q];

    const float* row = ssm + (size_t)b * LL * LDSSM;
    const float* xsr = xsum + b * LL;
    float nd = row[i], nbm = row[SS + i], nC = row[2 * SS + i], nxs = xsr[0];
    const float CLMP = -14.4269504088896340736f;           // -10*log2(e)

    for (int t = 0; t < LL; t++) {
        float draw = nd, bm = nbm, Cv = nC, xs = nxs;
        if (t + 1 < LL) {
            const float* r2 = row + (t + 1) * LDSSM;
            nd = r2[i]; nbm = r2[SS + i]; nC = r2[2 * SS + i]; nxs = xsr[t + 1];
        }
        float d = fmaxf(draw, 0.f) + log1pf(__expf(-fabsf(draw)));
        float db = d * bm;
        int par = t & 1;
        const float4* g4 = (const float4*)(gbuf[par] + sub * 16);
        float acc = 0.f;
#pragma unroll
        for (int q4 = 0; q4 < 4; q4++) {
            float4 gv = g4[q4];
            acc += tf32r(exp2f(fmaxf(d * Aj[q4 * 4 + 0], CLMP))) * gv.x;
            acc += tf32r(exp2f(fmaxf(d * Aj[q4 * 4 + 1], CLMP))) * gv.y;
            acc += tf32r(exp2f(fmaxf(d * Aj[q4 * 4 + 2], CLMP))) * gv.z;
            acc += tf32r(exp2f(fmaxf(d * Aj[q4 * 4 + 3], CLMP))) * gv.w;
        }
        acc += __shfl_xor_sync(0xffffffffu, acc, 1);
        acc += __shfl_xor_sync(0xffffffffu, acc, 2);
        int emit = (!lastonly) || (t == LL - 1);
        if (sub == 0) {
            float gn = acc + db * xs;
            gn = fminf(fmaxf(gn, -100.f), 100.f);
            float gr = tf32r(gn);
            gbuf[par ^ 1][i] = gr;
            if (emit) {
                float p = gr * tf32r(Cv);
                p += __shfl_xor_sync(0x11111111u, p, 4);
                p += __shfl_xor_sync(0x11111111u, p, 8);
                p += __shfl_xor_sync(0x11111111u, p, 16);
                if ((tid & 31) == 0) psum[tid >> 5] = p;
            }
        }
        __syncthreads();
        if (emit && tid == 0) {
            float t2 = 0.f;
#pragma unroll
            for (int w = 0; w < 8; w++) t2 += psum[w];
            sout[b * LL + t] = t2;
        }
    }
}

// y = s + D*x ; inner LN over E (two-pass); y *= silu(z). Warp per row.
// y stored tf32-rounded (feeds out-proj GEMM / lastout only).
__global__ void __launch_bounds__(256) act_kernel(
    const float* __restrict__ xc, const float* __restrict__ s_in,
    const float* __restrict__ xz, const float* __restrict__ D,
    const float* __restrict__ ig, const float* __restrict__ ib,
    float* __restrict__ y, int lastonly) {
    int warp = threadIdx.x >> 5, lane = threadIdx.x & 31;
    int r = blockIdx.x * 8 + warp;
    int m = lastonly ? (r * LL + (LL - 1)) : r;
    float sv = s_in[m];
    const float* xcr = xc + (size_t)m * EE;
    float yv[8];
    float tot = 0.f;
#pragma unroll
    for (int h = 0; h < 2; h++) {
        int e = (lane << 3) + (h << 2);
        float4 xv = *(const float4*)(xcr + e);
        float4 dv = *(const float4*)(D + e);
        yv[h * 4 + 0] = sv + dv.x * xv.x; yv[h * 4 + 1] = sv + dv.y * xv.y;
        yv[h * 4 + 2] = sv + dv.z * xv.z; yv[h * 4 + 3] = sv + dv.w * xv.w;
        tot += yv[h * 4 + 0] + yv[h * 4 + 1] + yv[h * 4 + 2] + yv[h * 4 + 3];
    }
    float mean = wredsum(tot) * (1.f / EE);
    float vs = 0.f;
#pragma unroll
    for (int q = 0; q < 8; q++) { yv[q] -= mean; vs += yv[q] * yv[q]; }
    float var = wredsum(vs) * (1.f / EE);
    float inv = rsqrtf(var + 1e-5f);
    const float* zr = xz + (size_t)m * LDXZ + EE;
#pragma unroll
    for (int h = 0; h < 2; h++) {
        int e = (lane << 3) + (h << 2);
        float4 gv = *(const float4*)(ig + e);
        float4 bv = *(const float4*)(ib + e);
        float4 zv = *(const float4*)(zr + e);
        float4 o;
        o.x = tf32r((yv[h*4+0] * inv * gv.x + bv.x) * (zv.x / (1.f + __expf(-zv.x))));
        o.y = tf32r((yv[h*4+1] * inv * gv.y + bv.y) * (zv.y / (1.f + __expf(-zv.y))));
        o.z = tf32r((yv[h*4+2] * inv * gv.z + bv.z) * (zv.z / (1.f + __expf(-zv.z))));
        o.w = tf32r((yv[h*4+3] * inv * gv.w + bv.w) * (zv.w / (1.f + __expf(-zv.w))));
        *(float4*)(y + (size_t)m * EE + e) = o;
    }
}

// small projection for last-timestep rows (block-2). A and W pre-rounded.
__global__ void lastproj_kernel(const float* __restrict__ A, int lda,
                                const float* __restrict__ W, int ldw,
                                const float* __restrict__ bias,
                                float* __restrict__ C, int ldc,
                                int Kdim, int ncols, int coloff) {
    int b = blockIdx.x;
    int row = b * LL + (LL - 1);
    __shared__ float ush[EE];
    int tid = threadIdx.x;
    if (tid < Kdim) ush[tid] = A[(size_t)row * lda + tid];
    __syncthreads();
    for (int n = tid; n < ncols; n += blockDim.x) {
        float acc = 0.f;
        const float* wp = W + coloff + n;
#pragma unroll 4
        for (int k = 0; k < Kdim; k++) acc += ush[k] * wp[(size_t)k * ldw];
        C[(size_t)row * ldc + coloff + n] = acc + bias[coloff + n];
    }
}

// out-proj + residual + mask for last-timestep rows (block 2). y/ow pre-rounded.
__global__ void lastout_kernel(const float* __restrict__ y, const float* __restrict__ ow,
                               const float* __restrict__ ob, const int* __restrict__ seqs,
                               float* __restrict__ x) {
    int b = blockIdx.x, h = threadIdx.x;   // 128 threads
    int row = b * LL + (LL - 1);
    __shared__ float ysh[EE];
    ysh[h] = y[(size_t)row * EE + h];
    ysh[h + HH] = y[(size_t)row * EE + h + HH];
    __syncthreads();
    float acc = 0.f;
#pragma unroll 4
    for (int e = 0; e < EE; e++) acc += ysh[e] * ow[e * HH + h];
    float v = x[(size_t)row * HH + h] + (acc + ob[h]);
    x[(size_t)row * HH + h] = (seqs[row] != 0) ? v : 0.f;
}

// final LN (last timestep only, two-pass) + logits vs candidates (tf32 dot)
__global__ void final_kernel(const float* __restrict__ x, const int* __restrict__ idxs,
                             const float* __restrict__ item_emb,
                             const float* __restrict__ fg, const float* __restrict__ fb,
                             float* __restrict__ out) {
    int b = blockIdx.x, tid = threadIdx.x;   // 128 threads
    const float* xr = x + (size_t)(b * LL + LL - 1) * HH;
    float v = xr[tid];
    __shared__ float sh1[4], sh2[4];
    float s1 = v;
#pragma unroll
    for (int o = 16; o; o >>= 1) s1 += __shfl_xor_sync(0xffffffffu, s1, o);
    if ((tid & 31) == 0) sh1[tid >> 5] = s1;
    __syncthreads();
    float mean = (sh1[0] + sh1[1] + sh1[2] + sh1[3]) * (1.f / HH);
    float d = v - mean;
    float s2 = d * d;
#pragma unroll
    for (int o = 16; o; o >>= 1) s2 += __shfl_xor_sync(0xffffffffu, s2, o);
    if ((tid & 31) == 0) sh2[tid >> 5] = s2;
    __syncthreads();
    float var = (sh2[0] + sh2[1] + sh2[2] + sh2[3]) * (1.f / HH);
    __shared__ float xn[HH];
    xn[tid] = tf32r(d * rsqrtf(var + 1e-5f) * fg[tid] + fb[tid]);
    __syncthreads();
    int warp = tid >> 5, lane = tid & 31;
    for (int k = warp; k < KC; k += 4) {
        const float* er = item_emb + (size_t)idxs[b * KC + k] * HH;
        float p = xn[lane] * tf32r(er[lane]) + xn[lane + 32] * tf32r(er[lane + 32])
                + xn[lane + 64] * tf32r(er[lane + 64]) + xn[lane + 96] * tf32r(er[lane + 96]);
#pragma unroll
        for (int o = 16; o; o >>= 1) p += __shfl_xor_sync(0xffffffffu, p, o);
        if (lane == 0) out[b * KC + k] = p;
    }
}

// ---------------------------------------------------------------------------
extern "C" void kernel_launch(void* const* d_in, const int* in_sizes, int n_in,
                              void* d_out, int out_size) {
    (void)in_sizes; (void)n_in; (void)out_size;
    const int*   seqs     = (const int*)d_in[0];
    const int*   idxs     = (const int*)d_in[1];
    const float* item_emb = (const float*)d_in[2];
    const float* pos_emb  = (const float*)d_in[3];
    const float* blk_ln_g = (const float*)d_in[4];
    const float* blk_ln_b = (const float*)d_in[5];
    const float* in_w     = (const float*)d_in[6];
    const float* in_b     = (const float*)d_in[7];
    const float* conv_w   = (const float*)d_in[8];
    const float* conv_b   = (const float*)d_in[9];
    const float* xproj_w  = (const float*)d_in[10];
    const float* xproj_b  = (const float*)d_in[11];
    const float* A_log    = (const float*)d_in[12];
    const float* D_param  = (const float*)d_in[13];
    const float* out_w    = (const float*)d_in[14];
    const float* out_b    = (const float*)d_in[15];
    const float* inner_g  = (const float*)d_in[16];
    const float* inner_b  = (const float*)d_in[17];
    const float* final_g  = (const float*)d_in[18];
    const float* final_b  = (const float*)d_in[19];
    float* outp = (float*)d_out;

    float *px, *pu, *pxz, *pxc, *pxcr, *pssm, *py, *pxsum, *ps, *pwr;
    cudaGetSymbolAddress((void**)&px, g_x);
    cudaGetSymbolAddress((void**)&pu, g_u);
    cudaGetSymbolAddress((void**)&pxz, g_xz);
    cudaGetSymbolAddress((void**)&pxc, g_xc);
    cudaGetSymbolAddress((void**)&pxcr, g_xcr);
    cudaGetSymbolAddress((void**)&pssm, g_ssm);
    cudaGetSymbolAddress((void**)&py, g_y);
    cudaGetSymbolAddress((void**)&pxsum, g_xsum);
    cudaGetSymbolAddress((void**)&ps, g_s);
    cudaGetSymbolAddress((void**)&pwr, g_wrnd);

    // pre-round all GEMM weights to tf32 once
    roundw_kernel<<<288, 256>>>((const float4*)in_w, 131072 / 4,
                                (const float4*)xproj_w, 98304 / 4,
                                (const float4*)out_w, 65536 / 4,
                                (float4*)pwr);

    for (int blk = 0; blk < NBLK; blk++) {
        const float* iw  = pwr + WR_INW   + (size_t)blk * HH * 2 * EE;
        const float* xw  = pwr + WR_XPROJ + (size_t)blk * EE * 3 * SS;
        const float* ow  = pwr + WR_OUTW  + (size_t)blk * EE * HH;
        const float* ibb = in_b    + blk * 2 * EE;
        const float* cw  = conv_w  + blk * EE * 3;
        const float* cb  = conv_b  + blk * EE;
        const float* xb  = xproj_b + blk * 3 * SS;
        const float* al  = A_log   + blk * SS;
        const float* dp  = D_param + blk * EE;
        const float* ob  = out_b   + blk * HH;
        const float* ig  = inner_g + blk * EE;
        const float* ibn = inner_b + blk * EE;

        if (blk == 0)
            embed_ln_kernel<<<MM / 8, 256>>>(seqs, item_emb, pos_emb,
                                             blk_ln_g, blk_ln_b, px, pu);
        else
            ln128_kernel<<<MM / 8, 256>>>(px, pu, blk_ln_g + blk * HH,
                                          blk_ln_b + blk * HH);

        int Nin = (blk == 0) ? (2 * EE) : EE;
        gemm_tc_kernel<<<dim3(Nin / 64, MM / 128), 256>>>(pu, HH, iw, 2 * EE, ibb,
                                                          pxz, 2 * EE, HH, 0, nullptr);
        if (blk == 1)
            lastproj_kernel<<<BB, 256>>>(pu, HH, iw, 2 * EE, ibb, pxz, 2 * EE,
                                         HH, EE, EE);

        conv_kernel<<<MM / 8, 256>>>(pxz, cw, cb, pxc, pxcr, pxsum);

        int Nxp = (blk == 0) ? (3 * SS) : (2 * SS);
        gemm_tc_kernel<<<dim3(Nxp / 64, MM / 128), 256>>>(pxcr, EE, xw, 3 * SS, xb,
                                                          pssm, LDSSM, EE, 0, nullptr);
        if (blk == 1)
            lastproj_kernel<<<BB, 256>>>(pxcr, EE, xw, 3 * SS, xb, pssm, LDSSM,
                                         EE, SS, 2 * SS);

        scan_kernel<<<BB, 256>>>(pssm, pxsum, al, ps, (blk == 1) ? 1 : 0);

        if (blk == 0) {
            act_kernel<<<MM / 8, 256>>>(pxc, ps, pxz, dp, ig, ibn, py, 0);
            gemm_tc_kernel<<<dim3(HH / 64, MM / 128), 256>>>(py, EE, ow, HH, ob,
                                                             px, HH, EE, 1, seqs);
        } else {
            act_kernel<<<BB / 8, 256>>>(pxc, ps, pxz, dp, ig, ibn, py, 1);
            lastout_kernel<<<BB, HH>>>(py, ow, ob, seqs, px);
        }
    }

    final_kernel<<<BB, HH>>>(px, idxs, item_emb, final_g, final_b, outp);
}

// round 14
// speedup vs baseline: 1.0480x; 1.0480x over previous
#include <cuda_runtime.h>
#include <cstdint>
#include <math.h>

#define BB 64
#define LL 200
#define HH 128
#define SS 64
#define EE 256
#define NBLK 2
#define MM (BB*LL)
#define KC 101
#define LDSSM 192
#define LDXZ (2*EE)

// TF32 round-to-nearest (matches tensor-core operand conversion).
__device__ __forceinline__ float tf32r(float x) {
    float r;
    asm("cvt.rna.tf32.f32 %0, %1;" : "=f"(r) : "f"(x));
    return r;
}

__device__ __forceinline__ void mma_tf32(float c[4],
    uint32_t a0, uint32_t a1, uint32_t a2, uint32_t a3,
    uint32_t b0, uint32_t b1) {
    asm volatile(
        "mma.sync.aligned.m16n8k8.row.col.f32.tf32.tf32.f32 "
        "{%0,%1,%2,%3}, {%4,%5,%6,%7}, {%8,%9}, {%0,%1,%2,%3};\n"
        : "+f"(c[0]), "+f"(c[1]), "+f"(c[2]), "+f"(c[3])
        : "r"(a0), "r"(a1), "r"(a2), "r"(a3), "r"(b0), "r"(b1));
}

__device__ __forceinline__ float wredsum(float v) {
#pragma unroll
    for (int o = 16; o; o >>= 1) v += __shfl_xor_sync(0xffffffffu, v, o);
    return v;
}

// Scratch (device globals — no allocation allowed)
__device__ __align__(16) float g_x[MM*HH];
__device__ __align__(16) float g_u[MM*HH];
__device__ __align__(16) float g_xz[MM*LDXZ];
__device__ __align__(16) float g_xc[MM*EE];
__device__ __align__(16) float g_ssm[MM*LDSSM];   // [delta_raw | B_raw | C]
__device__ __align__(16) float g_y[MM*EE];
__device__ __align__(16) float g_xsum[MM];
__device__ __align__(16) float g_s[MM];

// ---------------------------------------------------------------------------
// Fused embed + first-block LN. Warp handles rows m and m+MM/2 (2x MLP).
__global__ void __launch_bounds__(256) embed_ln_kernel(
    const int* __restrict__ seqs,
    const float* __restrict__ item_emb, const float* __restrict__ pos_emb,
    const float* __restrict__ g, const float* __restrict__ b,
    float* __restrict__ x, float* __restrict__ u) {
    int warp = threadIdx.x >> 5, lane = threadIdx.x & 31;
    int mA = blockIdx.x * 8 + warp;
    int e = lane << 2;
    float4 gg = *(const float4*)(g + e);
    float4 bb = *(const float4*)(b + e);
#pragma unroll
    for (int rr = 0; rr < 2; rr++) {
        int m = mA + rr * (MM / 2);
        int l = m % LL;
        int id = seqs[m];
        float4 ie = *(const float4*)(item_emb + (size_t)id * HH + e);
        float4 pe = *(const float4*)(pos_emb + l * HH + e);
        float msk = (id != 0) ? 1.f : 0.f;
        float4 v;
        v.x = (ie.x + pe.x) * msk; v.y = (ie.y + pe.y) * msk;
        v.z = (ie.z + pe.z) * msk; v.w = (ie.w + pe.w) * msk;
        *(float4*)(x + (size_t)m * HH + e) = v;
        float mean = wredsum(v.x + v.y + v.z + v.w) * (1.f / HH);
        float4 d; d.x = v.x - mean; d.y = v.y - mean; d.z = v.z - mean; d.w = v.w - mean;
        float var = wredsum(d.x * d.x + d.y * d.y + d.z * d.z + d.w * d.w) * (1.f / HH);
        float inv = rsqrtf(var + 1e-5f);
        float4 o;
        o.x = d.x * inv * gg.x + bb.x; o.y = d.y * inv * gg.y + bb.y;
        o.z = d.z * inv * gg.z + bb.z; o.w = d.w * inv * gg.w + bb.w;
        *(float4*)(u + (size_t)m * HH + e) = o;
    }
}

// LayerNorm over H=128. Warp handles rows m and m+MM/2. Two-pass variance.
__global__ void __launch_bounds__(256) ln128_kernel(
    const float* __restrict__ x, float* __restrict__ u,
    const float* __restrict__ g, const float* __restrict__ b) {
    int warp = threadIdx.x >> 5, lane = threadIdx.x & 31;
    int mA = blockIdx.x * 8 + warp;
    int e = lane << 2;
    float4 v0 = *(const float4*)(x + (size_t)mA * HH + e);
    float4 v1 = *(const float4*)(x + (size_t)(mA + MM / 2) * HH + e);
    float4 gg = *(const float4*)(g + e);
    float4 bb = *(const float4*)(b + e);
#pragma unroll
    for (int rr = 0; rr < 2; rr++) {
        int m = mA + rr * (MM / 2);
        float4 v = rr ? v1 : v0;
        float mean = wredsum(v.x + v.y + v.z + v.w) * (1.f / HH);
        float4 d; d.x = v.x - mean; d.y = v.y - mean; d.z = v.z - mean; d.w = v.w - mean;
        float var = wredsum(d.x * d.x + d.y * d.y + d.z * d.z + d.w * d.w) * (1.f / HH);
        float inv = rsqrtf(var + 1e-5f);
        float4 o;
        o.x = d.x * inv * gg.x + bb.x; o.y = d.y * inv * gg.y + bb.y;
        o.z = d.z * inv * gg.z + bb.z; o.w = d.w * inv * gg.w + bb.w;
        *(float4*)(u + (size_t)m * HH + e) = o;
    }
}

// ---------------------------------------------------------------------------
// TF32 tensor-core GEMM: C[M,N] = A[M,K] @ W[K,N] + bias.
// BM=64, BN=64, BK=16; 8 warps (4m x 2n), warp tile 16x32 via m16n8k8 tf32.
// Doubled grid vs BM=128 -> ~4-5 CTAs/SM for latency hiding.
// epi==1: C = (resid + C + bias) * mask (residual in C).
#define APAD 20
#define BPAD 72
__global__ void __launch_bounds__(256) gemm_tc_kernel(
    const float* __restrict__ A, int lda,
    const float* __restrict__ W, int ldw,
    const float* __restrict__ bias,
    float* __restrict__ C, int ldc,
    int Kdim, int epi, const int* __restrict__ seqs)
{
    __shared__ __align__(16) float As[2][64 * APAD];
    __shared__ __align__(16) float Ws[2][16 * BPAD];
    int tid = threadIdx.x;
    int m0 = blockIdx.y << 6, n0 = blockIdx.x << 6;
    int lane = tid & 31, wid = tid >> 5;
    int wm = (wid & 3) << 4;       // warp m offset: 0,16,32,48
    int wn = (wid >> 2) << 5;      // warp n offset: 0,32
    int g = lane >> 2, cq = lane & 3;

    int a_r = tid >> 2, a_q = tid & 3;          // A row a_r (0..63), quad a_q
    int b_k = tid >> 4, b_q = tid & 15;         // B row b_k, quad b_q
    const float* ApBase = A + (size_t)(m0 + a_r) * lda + (a_q << 2);
    const float* WpBase = W + (size_t)b_k * ldw + n0 + (b_q << 2);

    float acc[4][4];
#pragma unroll
    for (int j = 0; j < 4; j++)
#pragma unroll
        for (int q = 0; q < 4; q++) acc[j][q] = 0.f;

    float4 av = *(const float4*)(ApBase);
    float4 bv = *(const float4*)(WpBase);
    {
        float4 ta, tb;
        ta.x = tf32r(av.x); ta.y = tf32r(av.y); ta.z = tf32r(av.z); ta.w = tf32r(av.w);
        tb.x = tf32r(bv.x); tb.y = tf32r(bv.y); tb.z = tf32r(bv.z); tb.w = tf32r(bv.w);
        As[0][(a_q * 4 + 0) * 0 + a_r * APAD + (a_q << 2) + 0] = ta.x;  // row-major [m][k]
        As[0][a_r * APAD + (a_q << 2) + 1] = ta.y;
        As[0][a_r * APAD + (a_q << 2) + 2] = ta.z;
        As[0][a_r * APAD + (a_q << 2) + 3] = ta.w;
        *(float4*)&Ws[0][b_k * BPAD + (b_q << 2)] = tb;
    }
    __syncthreads();

    int nk = Kdim >> 4;
    for (int kt = 0; kt < nk; kt++) {
        int cur = kt & 1;
        if (kt + 1 < nk) {
            av = *(const float4*)(ApBase + ((kt + 1) << 4));
            bv = *(const float4*)(WpBase + (size_t)((kt + 1) << 4) * ldw);
        }
#pragma unroll
        for (int ks = 0; ks < 2; ks++) {
            int kk = ks << 3;
            uint32_t bf[4][2];
#pragma unroll
            for (int j = 0; j < 4; j++) {
                bf[j][0] = __float_as_uint(Ws[cur][(kk + cq) * BPAD + wn + (j << 3) + g]);
                bf[j][1] = __float_as_uint(Ws[cur][(kk + cq + 4) * BPAD + wn + (j << 3) + g]);
            }
            const float* ab = &As[cur][wm * APAD + kk + cq];
            uint32_t a0 = __float_as_uint(ab[g * APAD]);
            uint32_t a1 = __float_as_uint(ab[(g + 8) * APAD]);
            uint32_t a2 = __float_as_uint(ab[g * APAD + 4]);
            uint32_t a3 = __float_as_uint(ab[(g + 8) * APAD + 4]);
#pragma unroll
            for (int j = 0; j < 4; j++)
                mma_tf32(acc[j], a0, a1, a2, a3, bf[j][0], bf[j][1]);
        }
        if (kt + 1 < nk) {
            int nxt = cur ^ 1;
            float4 ta, tb;
            ta.x = tf32r(av.x); ta.y = tf32r(av.y); ta.z = tf32r(av.z); ta.w = tf32r(av.w);
            tb.x = tf32r(bv.x); tb.y = tf32r(bv.y); tb.z = tf32r(bv.z); tb.w = tf32r(bv.w);
            As[nxt][a_r * APAD + (a_q << 2) + 0] = ta.x;
            As[nxt][a_r * APAD + (a_q << 2) + 1] = ta.y;
            As[nxt][a_r * APAD + (a_q << 2) + 2] = ta.z;
            As[nxt][a_r * APAD + (a_q << 2) + 3] = ta.w;
            *(float4*)&Ws[nxt][b_k * BPAD + (b_q << 2)] = tb;
        }
        __syncthreads();
    }

    {
        int r0 = m0 + wm + g;
        int r1 = r0 + 8;
        float msk0 = 1.f, msk1 = 1.f;
        if (epi == 1) {
            msk0 = (seqs[r0] != 0) ? 1.f : 0.f;
            msk1 = (seqs[r1] != 0) ? 1.f : 0.f;
        }
#pragma unroll
        for (int j = 0; j < 4; j++) {
            int col = n0 + wn + (j << 3) + (cq << 1);
            float b0 = bias[col], b1 = bias[col + 1];
            size_t o0 = (size_t)r0 * ldc + col;
            size_t o1 = (size_t)r1 * ldc + col;
            float v00 = acc[j][0] + b0, v01 = acc[j][1] + b1;
            float v10 = acc[j][2] + b0, v11 = acc[j][3] + b1;
            if (epi == 1) {
                v00 = (C[o0] + v00) * msk0; v01 = (C[o0 + 1] + v01) * msk0;
                v10 = (C[o1] + v10) * msk1; v11 = (C[o1 + 1] + v11) * msk1;
            }
            C[o0] = v00; C[o0 + 1] = v01;
            C[o1] = v10; C[o1 + 1] = v11;
        }
    }
}

// depthwise conv k=3 pad (1,1) + silu + row-sum. Warp handles rows m and m+MM/2.
__global__ void __launch_bounds__(256) conv_kernel(
    const float* __restrict__ xz,
    const float* __restrict__ cw, const float* __restrict__ cb,
    float* __restrict__ xc, float* __restrict__ xsum) {
    int warp = threadIdx.x >> 5, lane = threadIdx.x & 31;
    int mA = blockIdx.x * 8 + warp;
#pragma unroll
    for (int rr = 0; rr < 2; rr++) {
        int m = mA + rr * (MM / 2);
        int l = m % LL;
        const float* xr = xz + (size_t)m * LDXZ;
        float s = 0.f;
#pragma unroll
        for (int h = 0; h < 2; h++) {
            int e = (lane << 3) + (h << 2);
            float4 vm = *(const float4*)(xr + e);
            float4 vl = (l > 0) ? *(const float4*)(xr - LDXZ + e) : make_float4(0.f, 0.f, 0.f, 0.f);
            float4 vh = (l < LL - 1) ? *(const float4*)(xr + LDXZ + e) : make_float4(0.f, 0.f, 0.f, 0.f);
            float am[4] = {vm.x, vm.y, vm.z, vm.w};
            float al[4] = {vl.x, vl.y, vl.z, vl.w};
            float ah[4] = {vh.x, vh.y, vh.z, vh.w};
            float out[4];
#pragma unroll
            for (int j = 0; j < 4; j++) {
                int ee = e + j;
                float acc = tf32r(am[j]) * tf32r(cw[ee * 3 + 1]);
                acc += tf32r(al[j]) * tf32r(cw[ee * 3 + 0]);
                acc += tf32r(ah[j]) * tf32r(cw[ee * 3 + 2]);
                acc += cb[ee];
                float sv = acc / (1.f + __expf(-acc));
                out[j] = sv;
                s += sv;
            }
            *(float4*)(xc + (size_t)m * EE + e) = make_float4(out[0], out[1], out[2], out[3]);
        }
        s = wredsum(s);
        if (lane == 0) xsum[m] = s;
    }
}

// Sequential scan with fused softplus/dB. Aj pre-scaled by log2(e).
__global__ void __launch_bounds__(256) scan_kernel(
    const float* __restrict__ ssm, const float* __restrict__ xsum,
    const float* __restrict__ A_log, float* __restrict__ sout, int lastonly)
{
    int b = blockIdx.x, tid = threadIdx.x;
    __shared__ float A_sh[SS];
    __shared__ __align__(16) float gbuf[2][SS];
    __shared__ float psum[8];
    if (tid < SS) {
        float al = A_log[tid];
        al = fminf(fmaxf(al, -5.f), 5.f);
        A_sh[tid] = -expf(al) * 1.44269504088896340736f;   // A * log2(e)
        gbuf[0][tid] = 0.f;
    }
    __syncthreads();
    int i = tid >> 2, sub = tid & 3;
    float Aj[16];
#pragma unroll
    for (int q = 0; q < 16; q++) Aj[q] = A_sh[sub * 16 + q];

    const float* row = ssm + (size_t)b * LL * LDSSM;
    const float* xsr = xsum + b * LL;
    float nd = row[i], nbm = row[SS + i], nC = row[2 * SS + i], nxs = xsr[0];
    const float CLMP = -14.4269504088896340736f;           // -10*log2(e)

    for (int t = 0; t < LL; t++) {
        float draw = nd, bm = nbm, Cv = nC, xs = nxs;
        if (t + 1 < LL) {
            const float* r2 = row + (t + 1) * LDSSM;
            nd = r2[i]; nbm = r2[SS + i]; nC = r2[2 * SS + i]; nxs = xsr[t + 1];
        }
        float d = fmaxf(draw, 0.f) + log1pf(__expf(-fabsf(draw)));
        float db = d * bm;
        int par = t & 1;
        const float4* g4 = (const float4*)(gbuf[par] + sub * 16);
        float acc = 0.f;
#pragma unroll
        for (int q4 = 0; q4 < 4; q4++) {
            float4 gv = g4[q4];
            acc += tf32r(exp2f(fmaxf(d * Aj[q4 * 4 + 0], CLMP))) * gv.x;
            acc += tf32r(exp2f(fmaxf(d * Aj[q4 * 4 + 1], CLMP))) * gv.y;
            acc += tf32r(exp2f(fmaxf(d * Aj[q4 * 4 + 2], CLMP))) * gv.z;
            acc += tf32r(exp2f(fmaxf(d * Aj[q4 * 4 + 3], CLMP))) * gv.w;
        }
        acc += __shfl_xor_sync(0xffffffffu, acc, 1);
        acc += __shfl_xor_sync(0xffffffffu, acc, 2);
        int emit = (!lastonly) || (t == LL - 1);
        if (sub == 0) {
            float gn = acc + db * xs;
            gn = fminf(fmaxf(gn, -100.f), 100.f);
            float gr = tf32r(gn);
            gbuf[par ^ 1][i] = gr;
            if (emit) {
                float p = gr * tf32r(Cv);
                p += __shfl_xor_sync(0x11111111u, p, 4);
                p += __shfl_xor_sync(0x11111111u, p, 8);
                p += __shfl_xor_sync(0x11111111u, p, 16);
                if ((tid & 31) == 0) psum[tid >> 5] = p;
            }
        }
        __syncthreads();
        if (emit && tid == 0) {
            float t2 = 0.f;
#pragma unroll
            for (int w = 0; w < 8; w++) t2 += psum[w];
            sout[b * LL + t] = t2;
        }
    }
}

// y = s + D*x ; inner LN over E (two-pass); y *= silu(z). Warp handles 2 rows.
__global__ void __launch_bounds__(256) act_kernel(
    const float* __restrict__ xc, const float* __restrict__ s_in,
    const float* __restrict__ xz, const float* __restrict__ D,
    const float* __restrict__ ig, const float* __restrict__ ib,
    float* __restrict__ y, int lastonly, int halfstride) {
    int warp = threadIdx.x >> 5, lane = threadIdx.x & 31;
    int rA = blockIdx.x * 8 + warp;
#pragma unroll
    for (int rr = 0; rr < 2; rr++) {
        int r = rA + rr * halfstride;
        int m = lastonly ? (r * LL + (LL - 1)) : r;
        float sv = s_in[m];
        const float* xcr = xc + (size_t)m * EE;
        float yv[8];
        float tot = 0.f;
#pragma unroll
        for (int h = 0; h < 2; h++) {
            int e = (lane << 3) + (h << 2);
            float4 xv = *(const float4*)(xcr + e);
            float4 dv = *(const float4*)(D + e);
            yv[h * 4 + 0] = sv + dv.x * xv.x; yv[h * 4 + 1] = sv + dv.y * xv.y;
            yv[h * 4 + 2] = sv + dv.z * xv.z; yv[h * 4 + 3] = sv + dv.w * xv.w;
            tot += yv[h * 4 + 0] + yv[h * 4 + 1] + yv[h * 4 + 2] + yv[h * 4 + 3];
        }
        float mean = wredsum(tot) * (1.f / EE);
        float vs = 0.f;
#pragma unroll
        for (int q = 0; q < 8; q++) { yv[q] -= mean; vs += yv[q] * yv[q]; }
        float var = wredsum(vs) * (1.f / EE);
        float inv = rsqrtf(var + 1e-5f);
        const float* zr = xz + (size_t)m * LDXZ + EE;
#pragma unroll
        for (int h = 0; h < 2; h++) {
            int e = (lane << 3) + (h << 2);
            float4 gv = *(const float4*)(ig + e);
            float4 bv = *(const float4*)(ib + e);
            float4 zv = *(const float4*)(zr + e);
            float4 o;
            o.x = (yv[h*4+0] * inv * gv.x + bv.x) * (zv.x / (1.f + __expf(-zv.x)));
            o.y = (yv[h*4+1] * inv * gv.y + bv.y) * (zv.y / (1.f + __expf(-zv.y)));
            o.z = (yv[h*4+2] * inv * gv.z + bv.z) * (zv.z / (1.f + __expf(-zv.z)));
            o.w = (yv[h*4+3] * inv * gv.w + bv.w) * (zv.w / (1.f + __expf(-zv.w)));
            *(float4*)(y + (size_t)m * EE + e) = o;
        }
    }
}

// small projection for last-timestep rows (block-2 z-half / C-cols)
__global__ void lastproj_kernel(const float* __restrict__ A, int lda,
                                const float* __restrict__ W, int ldw,
                                const float* __restrict__ bias,
                                float* __restrict__ C, int ldc,
                                int Kdim, int ncols, int coloff) {
    int b = blockIdx.x;
    int row = b * LL + (LL - 1);
    __shared__ float ush[EE];
    int tid = threadIdx.x;
    if (tid < Kdim) ush[tid] = tf32r(A[(size_t)row * lda + tid]);
    __syncthreads();
    for (int n = tid; n < ncols; n += blockDim.x) {
        float acc = 0.f;
        const float* wp = W + coloff + n;
#pragma unroll 4
        for (int k = 0; k < Kdim; k++) acc += ush[k] * tf32r(wp[(size_t)k * ldw]);
        C[(size_t)row * ldc + coloff + n] = acc + bias[coloff + n];
    }
}

// out-proj + residual + mask for last-timestep rows (block 2)
__global__ void lastout_kernel(const float* __restrict__ y, const float* __restrict__ ow,
                               const float* __restrict__ ob, const int* __restrict__ seqs,
                               float* __restrict__ x) {
    int b = blockIdx.x, h = threadIdx.x;   // 128 threads
    int row = b * LL + (LL - 1);
    __shared__ float ysh[EE];
    ysh[h] = tf32r(y[(size_t)row * EE + h]);
    ysh[h + HH] = tf32r(y[(size_t)row * EE + h + HH]);
    __syncthreads();
    float acc = 0.f;
#pragma unroll 4
    for (int e = 0; e < EE; e++) acc += ysh[e] * tf32r(ow[e * HH + h]);
    float v = x[(size_t)row * HH + h] + (acc + ob[h]);
    x[(size_t)row * HH + h] = (seqs[row] != 0) ? v : 0.f;
}

// final LN (last timestep only, two-pass) + logits vs candidates (tf32 dot)
__global__ void final_kernel(const float* __restrict__ x, const int* __restrict__ idxs,
                             const float* __restrict__ item_emb,
                             const float* __restrict__ fg, const float* __restrict__ fb,
                             float* __restrict__ out) {
    int b = blockIdx.x, tid = threadIdx.x;   // 128 threads
    const float* xr = x + (size_t)(b * LL + LL - 1) * HH;
    float v = xr[tid];
    __shared__ float sh1[4], sh2[4];
    float s1 = v;
#pragma unroll
    for (int o = 16; o; o >>= 1) s1 += __shfl_xor_sync(0xffffffffu, s1, o);
    if ((tid & 31) == 0) sh1[tid >> 5] = s1;
    __syncthreads();
    float mean = (sh1[0] + sh1[1] + sh1[2] + sh1[3]) * (1.f / HH);
    float d = v - mean;
    float s2 = d * d;
#pragma unroll
    for (int o = 16; o; o >>= 1) s2 += __shfl_xor_sync(0xffffffffu, s2, o);
    if ((tid & 31) == 0) sh2[tid >> 5] = s2;
    __syncthreads();
    float var = (sh2[0] + sh2[1] + sh2[2] + sh2[3]) * (1.f / HH);
    __shared__ float xn[HH];
    xn[tid] = tf32r(d * rsqrtf(var + 1e-5f) * fg[tid] + fb[tid]);
    __syncthreads();
    int warp = tid >> 5, lane = tid & 31;
    for (int k = warp; k < KC; k += 4) {
        const float* er = item_emb + (size_t)idxs[b * KC + k] * HH;
        float p = xn[lane] * tf32r(er[lane]) + xn[lane + 32] * tf32r(er[lane + 32])
                + xn[lane + 64] * tf32r(er[lane + 64]) + xn[lane + 96] * tf32r(er[lane + 96]);
#pragma unroll
        for (int o = 16; o; o >>= 1) p += __shfl_xor_sync(0xffffffffu, p, o);
        if (lane == 0) out[b * KC + k] = p;
    }
}

// ---------------------------------------------------------------------------
extern "C" void kernel_launch(void* const* d_in, const int* in_sizes, int n_in,
                              void* d_out, int out_size) {
    (void)in_sizes; (void)n_in; (void)out_size;
    const int*   seqs     = (const int*)d_in[0];
    const int*   idxs     = (const int*)d_in[1];
    const float* item_emb = (const float*)d_in[2];
    const float* pos_emb  = (const float*)d_in[3];
    const float* blk_ln_g = (const float*)d_in[4];
    const float* blk_ln_b = (const float*)d_in[5];
    const float* in_w     = (const float*)d_in[6];
    const float* in_b     = (const float*)d_in[7];
    const float* conv_w   = (const float*)d_in[8];
    const float* conv_b   = (const float*)d_in[9];
    const float* xproj_w  = (const float*)d_in[10];
    const float* xproj_b  = (const float*)d_in[11];
    const float* A_log    = (const float*)d_in[12];
    const float* D_param  = (const float*)d_in[13];
    const float* out_w    = (const float*)d_in[14];
    const float* out_b    = (const float*)d_in[15];
    const float* inner_g  = (const float*)d_in[16];
    const float* inner_b  = (const float*)d_in[17];
    const float* final_g  = (const float*)d_in[18];
    const float* final_b  = (const float*)d_in[19];
    float* outp = (float*)d_out;

    float *px, *pu, *pxz, *pxc, *pssm, *py, *pxsum, *ps;
    cudaGetSymbolAddress((void**)&px, g_x);
    cudaGetSymbolAddress((void**)&pu, g_u);
    cudaGetSymbolAddress((void**)&pxz, g_xz);
    cudaGetSymbolAddress((void**)&pxc, g_xc);
    cudaGetSymbolAddress((void**)&pssm, g_ssm);
    cudaGetSymbolAddress((void**)&py, g_y);
    cudaGetSymbolAddress((void**)&pxsum, g_xsum);
    cudaGetSymbolAddress((void**)&ps, g_s);

    for (int blk = 0; blk < NBLK; blk++) {
        const float* iw  = in_w    + (size_t)blk * HH * 2 * EE;
        const float* ibb = in_b    + blk * 2 * EE;
        const float* cw  = conv_w  + blk * EE * 3;
        const float* cb  = conv_b  + blk * EE;
        const float* xw  = xproj_w + (size_t)blk * EE * 3 * SS;
        const float* xb  = xproj_b + blk * 3 * SS;
        const float* al  = A_log   + blk * SS;
        const float* dp  = D_param + blk * EE;
        const float* ow  = out_w   + (size_t)blk * EE * HH;
        const float* ob  = out_b   + blk * HH;
        const float* ig  = inner_g + blk * EE;
        const float* ibn = inner_b + blk * EE;

        if (blk == 0)
            embed_ln_kernel<<<MM / 16, 256>>>(seqs, item_emb, pos_emb,
                                              blk_ln_g, blk_ln_b, px, pu);
        else
            ln128_kernel<<<MM / 16, 256>>>(px, pu, blk_ln_g + blk * HH,
                                           blk_ln_b + blk * HH);

        int Nin = (blk == 0) ? (2 * EE) : EE;
        gemm_tc_kernel<<<dim3(Nin / 64, MM / 64), 256>>>(pu, HH, iw, 2 * EE, ibb,
                                                         pxz, 2 * EE, HH, 0, nullptr);
        if (blk == 1)
            lastproj_kernel<<<BB, 256>>>(pu, HH, iw, 2 * EE, ibb, pxz, 2 * EE,
                                         HH, EE, EE);

        conv_kernel<<<MM / 16, 256>>>(pxz, cw, cb, pxc, pxsum);

        int Nxp = (blk == 0) ? (3 * SS) : (2 * SS);
        gemm_tc_kernel<<<dim3(Nxp / 64, MM / 64), 256>>>(pxc, EE, xw, 3 * SS, xb,
                                                         pssm, LDSSM, EE, 0, nullptr);
        if (blk == 1)
            lastproj_kernel<<<BB, 256>>>(pxc, EE, xw, 3 * SS, xb, pssm, LDSSM,
                                         EE, SS, 2 * SS);

        scan_kernel<<<BB, 256>>>(pssm, pxsum, al, ps, (blk == 1) ? 1 : 0);

        if (blk == 0) {
            act_kernel<<<MM / 16, 256>>>(pxc, ps, pxz, dp, ig, ibn, py, 0, MM / 2);
            gemm_tc_kernel<<<dim3(HH / 64, MM / 64), 256>>>(py, EE, ow, HH, ob,
                                                            px, HH, EE, 1, seqs);
        } else {
            act_kernel<<<BB / 16, 256>>>(pxc, ps, pxz, dp, ig, ibn, py, 1, BB / 2);
            lastout_kernel<<<BB, HH>>>(py, ow, ob, seqs, px);
        }
    }

    final_kernel<<<BB, HH>>>(px, idxs, item_emb, final_g, final_b, outp);
}